// round 6
// baseline (speedup 1.0000x reference)
#include <cuda_runtime.h>
#include <cstddef>

// ---------------- problem constants ----------------
#define BATCH 16
#define NPTS  1024              // N == M
#define DIM   64
#define L2E_EPS 144.2695040888963f       // log2(e) / eps, eps = 0.01
#define EPS_LN2 0.006931471805599453f    // eps * ln(2)
#define EPS_LOG_A (-0.06931461565651899f) // eps * log(1/1024 + 1e-8)  (== eps*log_b)
#define SKIP_THR 40.0f                   // drop terms < 2^-40 of max

#define NSLAB 4                 // row slabs in col pass
#define NGRP  (BATCH * 32)      // column groups (32 cols each) = 512

// ---------------- device state (no cudaMalloc allowed) ----------------
__device__ float    g_C[BATCH * NPTS * NPTS];   // 64 MB cost matrix
__device__ float    g_u[BATCH * NPTS];
__device__ float    g_v[BATCH * NPTS];
__device__ float    g_xn[BATCH * NPTS];
__device__ float    g_yn[BATCH * NPTS];
__device__ float    g_du[BATCH];
__device__ float    g_dv[BATCH];
__device__ int      g_done;
__device__ unsigned g_ticket;
__device__ unsigned g_gtick[NGRP];
__device__ float2   g_cpart[NGRP * NSLAB * 32];
__device__ float    g_part[2048];

// ---------------- helpers ----------------
__device__ __forceinline__ float ex2f(float x) {
    float y; asm("ex2.approx.ftz.f32 %0, %1;" : "=f"(y) : "f"(x)); return y;
}
__device__ __forceinline__ float lg2f(float x) {
    float y; asm("lg2.approx.f32 %0, %1;" : "=f"(y) : "f"(x)); return y;
}
__device__ __forceinline__ void lse_merge(float& m, float& s, float m2, float s2) {
    float M = fmaxf(m, m2);
    s = fmaf(s, ex2f(m - M), s2 * ex2f(m2 - M));
    m = M;
}

// ---------------- init: norms + state reset ----------------
__global__ __launch_bounds__(256) void init_kernel(float* __restrict__ out,
                                                   const float* __restrict__ x,
                                                   const float* __restrict__ y) {
    int tid = threadIdx.x, w = tid >> 5, lane = tid & 31;
    int r = blockIdx.x * 8 + w;
    bool is_x = (r < BATCH * NPTS);
    const float* src = is_x ? (x + (size_t)r * DIM)
                            : (y + (size_t)(r - BATCH * NPTS) * DIM);
    float a = src[lane], b = src[lane + 32];
    float sq = a * a + b * b;
    #pragma unroll
    for (int o = 16; o; o >>= 1) sq += __shfl_xor_sync(0xffffffffu, sq, o);
    if (lane == 0) {
        if (is_x) g_xn[r] = sq; else g_yn[r - BATCH * NPTS] = sq;
    }
    int g = blockIdx.x * 256 + tid;
    if (g < BATCH * NPTS) { g_u[g] = 0.0f; g_v[g] = 0.0f; }
    if (g < BATCH) { g_du[g] = 0.0f; g_dv[g] = 0.0f; out[g] = 0.0f; }
    if (g < NGRP) g_gtick[g] = 0u;
    if (g == 0) { g_done = 0; g_ticket = 0u; }
}

// ---------------- build C = |x|^2 + |y|^2 - 2 x.y ----------------
__global__ __launch_bounds__(256) void c_kernel(const float* __restrict__ x,
                                                const float* __restrict__ y) {
    __shared__ float xs[64][65];
    __shared__ float ys[64][65];
    int tid = threadIdx.x;
    int b = blockIdx.z, i0 = blockIdx.y * 64, j0 = blockIdx.x * 64;
    const float* xb = x + ((size_t)(b * NPTS + i0)) * DIM;
    const float* yb = y + ((size_t)(b * NPTS + j0)) * DIM;
    #pragma unroll
    for (int t = 0; t < 4; t++) {
        int e = tid + t * 256;
        int row = e >> 4, c4 = (e & 15) * 4;
        float4 vx = *(const float4*)(xb + row * DIM + c4);
        xs[row][c4] = vx.x; xs[row][c4 + 1] = vx.y; xs[row][c4 + 2] = vx.z; xs[row][c4 + 3] = vx.w;
        float4 vy = *(const float4*)(yb + row * DIM + c4);
        ys[row][c4] = vy.x; ys[row][c4 + 1] = vy.y; ys[row][c4 + 2] = vy.z; ys[row][c4 + 3] = vy.w;
    }
    __syncthreads();
    int tx = tid & 15, ty = tid >> 4;
    float acc[4][4];
    #pragma unroll
    for (int r = 0; r < 4; r++)
        #pragma unroll
        for (int c = 0; c < 4; c++) acc[r][c] = 0.0f;
    #pragma unroll 16
    for (int d = 0; d < 64; d++) {
        float a0 = xs[ty * 4 + 0][d], a1 = xs[ty * 4 + 1][d];
        float a2 = xs[ty * 4 + 2][d], a3 = xs[ty * 4 + 3][d];
        float b0 = ys[tx * 4 + 0][d], b1 = ys[tx * 4 + 1][d];
        float b2 = ys[tx * 4 + 2][d], b3 = ys[tx * 4 + 3][d];
        acc[0][0] = fmaf(a0, b0, acc[0][0]); acc[0][1] = fmaf(a0, b1, acc[0][1]);
        acc[0][2] = fmaf(a0, b2, acc[0][2]); acc[0][3] = fmaf(a0, b3, acc[0][3]);
        acc[1][0] = fmaf(a1, b0, acc[1][0]); acc[1][1] = fmaf(a1, b1, acc[1][1]);
        acc[1][2] = fmaf(a1, b2, acc[1][2]); acc[1][3] = fmaf(a1, b3, acc[1][3]);
        acc[2][0] = fmaf(a2, b0, acc[2][0]); acc[2][1] = fmaf(a2, b1, acc[2][1]);
        acc[2][2] = fmaf(a2, b2, acc[2][2]); acc[2][3] = fmaf(a2, b3, acc[2][3]);
        acc[3][0] = fmaf(a3, b0, acc[3][0]); acc[3][1] = fmaf(a3, b1, acc[3][1]);
        acc[3][2] = fmaf(a3, b2, acc[3][2]); acc[3][3] = fmaf(a3, b3, acc[3][3]);
    }
    float* Cb = g_C + ((size_t)b << 20);
    float yn0 = g_yn[b * NPTS + j0 + tx * 4 + 0];
    float yn1 = g_yn[b * NPTS + j0 + tx * 4 + 1];
    float yn2 = g_yn[b * NPTS + j0 + tx * 4 + 2];
    float yn3 = g_yn[b * NPTS + j0 + tx * 4 + 3];
    #pragma unroll
    for (int r = 0; r < 4; r++) {
        int i = i0 + ty * 4 + r;
        float xni = g_xn[b * NPTS + i];
        float4 o;
        o.x = xni + yn0 - 2.0f * acc[r][0];
        o.y = xni + yn1 - 2.0f * acc[r][1];
        o.z = xni + yn2 - 2.0f * acc[r][2];
        o.w = xni + yn3 - 2.0f * acc[r][3];
        *(float4*)(Cb + (size_t)i * NPTS + j0 + tx * 4) = o;
    }
}

// ---------------- row update ----------------
// grid 2048 x 256: one warp per row. All 32 elements in registers, exact
// full-row max first, then vote-gated ex2 sums (skip chunks < max-40).
__global__ __launch_bounds__(256) void row_kernel() {
    if (g_done) return;
    __shared__ float sh_vL[NPTS];
    __shared__ float sh_du[8];
    int tid = threadIdx.x, w = tid >> 5, lane = tid & 31;
    int row = blockIdx.x * 8 + w;
    int b = row >> 10;
    const float* vb = g_v + (b << 10);
    for (int t = tid; t < NPTS; t += 256) sh_vL[t] = vb[t] * L2E_EPS;
    __syncthreads();
    const float* Crow = g_C + ((size_t)row << 10);

    float wv[32];
    #pragma unroll
    for (int k = 0; k < 8; k++) {
        int j = k * 128 + lane * 4;
        float4 c  = *(const float4*)(Crow + j);
        float4 vl = *(const float4*)(sh_vL + j);
        wv[k * 4 + 0] = fmaf(c.x, -L2E_EPS, vl.x);
        wv[k * 4 + 1] = fmaf(c.y, -L2E_EPS, vl.y);
        wv[k * 4 + 2] = fmaf(c.z, -L2E_EPS, vl.z);
        wv[k * 4 + 3] = fmaf(c.w, -L2E_EPS, vl.w);
    }
    // chunk maxes (8 elements each) + thread max
    float gm[4];
    #pragma unroll
    for (int k = 0; k < 4; k++) {
        float t0 = fmaxf(wv[k * 8 + 0], wv[k * 8 + 1]);
        float t1 = fmaxf(wv[k * 8 + 2], wv[k * 8 + 3]);
        float t2 = fmaxf(wv[k * 8 + 4], wv[k * 8 + 5]);
        float t3 = fmaxf(wv[k * 8 + 6], wv[k * 8 + 7]);
        gm[k] = fmaxf(fmaxf(t0, t1), fmaxf(t2, t3));
    }
    float M = fmaxf(fmaxf(gm[0], gm[1]), fmaxf(gm[2], gm[3]));
    #pragma unroll
    for (int o = 16; o; o >>= 1) M = fmaxf(M, __shfl_xor_sync(0xffffffffu, M, o));
    // vote-gated exp sums
    float s = 0.0f;
    float thr = M - SKIP_THR;
    #pragma unroll
    for (int k = 0; k < 4; k++) {
        if (__any_sync(0xffffffffu, gm[k] > thr)) {
            float s0 = ex2f(wv[k * 8 + 0] - M) + ex2f(wv[k * 8 + 4] - M);
            float s1 = ex2f(wv[k * 8 + 1] - M) + ex2f(wv[k * 8 + 5] - M);
            float s2 = ex2f(wv[k * 8 + 2] - M) + ex2f(wv[k * 8 + 6] - M);
            float s3 = ex2f(wv[k * 8 + 3] - M) + ex2f(wv[k * 8 + 7] - M);
            s += (s0 + s1) + (s2 + s3);
        }
    }
    #pragma unroll
    for (int o = 16; o; o >>= 1) s += __shfl_xor_sync(0xffffffffu, s, o);
    if (lane == 0) {
        float u_new = EPS_LOG_A - EPS_LN2 * (M + lg2f(s));
        float u_old = g_u[row];
        g_u[row] = u_new;
        sh_du[w] = fabsf(u_new - u_old);
    }
    __syncthreads();
    if (tid == 0) {
        float a = 0.0f;
        #pragma unroll
        for (int i = 0; i < 8; i++) a += sh_du[i];
        atomicAdd(&g_du[b], a);
    }
}

// ---------------- col update ----------------
// grid 2048 x 256: CTA = (batch, colgroup 32 cols, slab 256 rows).
// Thread owns 32 rows of one column: all loads up front (MLP=32), tree max,
// slab max via smem, vote-gated ex2 sums. Slab partials merged by last CTA.
__global__ __launch_bounds__(256) void col_kernel() {
    if (g_done) return;
    __shared__ float sh_uL[256];
    __shared__ float sh_m[256];
    __shared__ float sh_s[256];
    __shared__ unsigned sh_last;
    int tid  = threadIdx.x;
    int grp  = blockIdx.x >> 2;
    int slab = blockIdx.x & 3;
    int b    = grp >> 5;
    int j0   = (grp & 31) * 32;
    int r0   = slab * 256;
    const float* ub = g_u + (b << 10) + r0;
    sh_uL[tid] = ub[tid] * L2E_EPS;
    __syncthreads();
    int c = tid & 31;
    int g = tid >> 5;
    const float* Cp = g_C + (((size_t)(b << 10) + r0 + g * 32) << 10) + (j0 + c);

    float wv[32];
    #pragma unroll
    for (int r = 0; r < 32; r++) wv[r] = __ldg(Cp + ((size_t)r << 10));
    #pragma unroll
    for (int r = 0; r < 32; r++) wv[r] = fmaf(wv[r], -L2E_EPS, sh_uL[g * 32 + r]);

    float gm[4];
    #pragma unroll
    for (int k = 0; k < 4; k++) {
        float t0 = fmaxf(wv[k * 8 + 0], wv[k * 8 + 1]);
        float t1 = fmaxf(wv[k * 8 + 2], wv[k * 8 + 3]);
        float t2 = fmaxf(wv[k * 8 + 4], wv[k * 8 + 5]);
        float t3 = fmaxf(wv[k * 8 + 6], wv[k * 8 + 7]);
        gm[k] = fmaxf(fmaxf(t0, t1), fmaxf(t2, t3));
    }
    float Mt = fmaxf(fmaxf(gm[0], gm[1]), fmaxf(gm[2], gm[3]));
    sh_m[tid] = Mt;
    __syncthreads();
    // slab max per column (identical value computed by all 8 threads of column c)
    float Ms = sh_m[c];
    #pragma unroll
    for (int gg = 1; gg < 8; gg++) Ms = fmaxf(Ms, sh_m[gg * 32 + c]);
    float thr = Ms - SKIP_THR;
    float s = 0.0f;
    #pragma unroll
    for (int k = 0; k < 4; k++) {
        if (__any_sync(0xffffffffu, gm[k] > thr)) {
            float s0 = ex2f(wv[k * 8 + 0] - Ms) + ex2f(wv[k * 8 + 4] - Ms);
            float s1 = ex2f(wv[k * 8 + 1] - Ms) + ex2f(wv[k * 8 + 5] - Ms);
            float s2 = ex2f(wv[k * 8 + 2] - Ms) + ex2f(wv[k * 8 + 6] - Ms);
            float s3 = ex2f(wv[k * 8 + 3] - Ms) + ex2f(wv[k * 8 + 7] - Ms);
            s += (s0 + s1) + (s2 + s3);
        }
    }
    sh_s[tid] = s;
    __syncthreads();
    if (tid < 32) {
        float S = sh_s[tid];
        #pragma unroll
        for (int gg = 1; gg < 8; gg++) S += sh_s[gg * 32 + tid];
        g_cpart[(grp * NSLAB + slab) * 32 + tid] = make_float2(Ms, S);
    }
    __syncthreads();
    if (tid == 0) {
        __threadfence();
        sh_last = atomicAdd(&g_gtick[grp], 1u);
    }
    __syncthreads();
    if (sh_last != NSLAB - 1) return;

    if (tid < 32) {
        const float2* P = g_cpart + (size_t)grp * NSLAB * 32;
        float2 p0 = __ldcg(&P[0 * 32 + tid]);
        float2 p1 = __ldcg(&P[1 * 32 + tid]);
        float2 p2 = __ldcg(&P[2 * 32 + tid]);
        float2 p3 = __ldcg(&P[3 * 32 + tid]);
        float M = p0.x, S = p0.y;
        lse_merge(M, S, p1.x, p1.y);
        lse_merge(M, S, p2.x, p2.y);
        lse_merge(M, S, p3.x, p3.y);
        float v_new = EPS_LOG_A - EPS_LN2 * (M + lg2f(S));
        int vidx = (b << 10) + j0 + tid;
        float v_old = g_v[vidx];
        g_v[vidx] = v_new;
        float dv = fabsf(v_new - v_old);
        #pragma unroll
        for (int o = 16; o; o >>= 1) dv += __shfl_xor_sync(0xffffffffu, dv, o);
        if (tid == 0) {
            g_gtick[grp] = 0u;
            atomicAdd(&g_dv[b], dv);
            __threadfence();
            unsigned t = atomicAdd(&g_ticket, 1u);
            if (t == NGRP - 1) {
                float diff = 0.0f;
                for (int bb = 0; bb < BATCH; bb++) {
                    diff += g_du[bb] + g_dv[bb];
                    g_du[bb] = 0.0f; g_dv[bb] = 0.0f;
                }
                diff *= (1.0f / BATCH);
                if (diff < 1e-4f) g_done = 1;
                g_ticket = 0u;
            }
        }
    }
}

// ---------------- final cost ----------------
__global__ __launch_bounds__(256) void cost_kernel() {
    __shared__ float sh_vL[NPTS];
    __shared__ float sh_acc[8];
    int tid = threadIdx.x, w = tid >> 5, lane = tid & 31;
    int row = blockIdx.x * 8 + w;
    int b = row >> 10;
    const float* vb = g_v + (b << 10);
    for (int t = tid; t < NPTS; t += 256) sh_vL[t] = vb[t] * L2E_EPS;
    __syncthreads();
    float uL = g_u[row] * L2E_EPS;
    const float* Crow = g_C + ((size_t)row << 10);
    float acc = 0.0f;
    #pragma unroll
    for (int k = 0; k < 8; k++) {
        int j = k * 128 + lane * 4;
        float4 c  = *(const float4*)(Crow + j);
        float4 vl = *(const float4*)(sh_vL + j);
        float p;
        p = ex2f(fmaf(c.x, -L2E_EPS, uL + vl.x)); acc = fmaf(p, c.x, acc);
        p = ex2f(fmaf(c.y, -L2E_EPS, uL + vl.y)); acc = fmaf(p, c.y, acc);
        p = ex2f(fmaf(c.z, -L2E_EPS, uL + vl.z)); acc = fmaf(p, c.z, acc);
        p = ex2f(fmaf(c.w, -L2E_EPS, uL + vl.w)); acc = fmaf(p, c.w, acc);
    }
    #pragma unroll
    for (int o = 16; o; o >>= 1) acc += __shfl_xor_sync(0xffffffffu, acc, o);
    if (lane == 0) sh_acc[w] = acc;
    __syncthreads();
    if (tid == 0) {
        float t = 0.0f;
        #pragma unroll
        for (int i = 0; i < 8; i++) t += sh_acc[i];
        g_part[blockIdx.x] = t;
    }
}

__global__ __launch_bounds__(256) void cost_final(float* __restrict__ out) {
    int tid = threadIdx.x;
    int b = tid >> 4, idx = tid & 15;
    float s = 0.0f;
    #pragma unroll
    for (int k = 0; k < 8; k++) s += g_part[b * 128 + idx * 8 + k];
    #pragma unroll
    for (int o = 8; o; o >>= 1) s += __shfl_xor_sync(0xffffffffu, s, o);
    if (idx == 0) out[b] = s;
}

// ---------------- launch ----------------
extern "C" void kernel_launch(void* const* d_in, const int* in_sizes, int n_in,
                              void* d_out, int out_size) {
    (void)in_sizes; (void)n_in; (void)out_size;
    const float* x = (const float*)d_in[0];
    const float* y = (const float*)d_in[1];
    float* out = (float*)d_out;

    init_kernel<<<4096, 256>>>(out, x, y);
    c_kernel<<<dim3(16, 16, 16), 256>>>(x, y);
    for (int it = 0; it < 100; ++it) {
        row_kernel<<<2048, 256>>>();
        col_kernel<<<2048, 256>>>();
    }
    cost_kernel<<<2048, 256>>>();
    cost_final<<<1, 256>>>(out);
}

// round 7
// speedup vs baseline: 1.8058x; 1.8058x over previous
#include <cuda_runtime.h>
#include <cstddef>

// ---------------- problem constants ----------------
#define BATCH 16
#define NPTS  1024              // N == M
#define DIM   64
#define L2E_EPS 144.2695040888963f   // log2(e)/eps, eps = 0.01
#define LOG2_A  (-9.999985227f)      // log2(1/1024 + 1e-8)
#define SKIP_THR 40.0f               // drop terms < 2^-40 of max (row pass)
#define GRID  (BATCH * 32)           // 512 CTAs, 32 per batch
#define ITERS 100

// ---------------- device state (no cudaMalloc allowed) ----------------
__device__ float    g_C[BATCH * NPTS * NPTS];   // 64 MB cost matrix
__device__ float    g_uL[BATCH * NPTS];         // u * log2e/eps
__device__ float    g_vL[BATCH * NPTS];         // v * log2e/eps
__device__ float    g_xn[BATCH * NPTS];
__device__ float    g_yn[BATCH * NPTS];
__device__ unsigned g_bar[BATCH];               // monotonic per-batch barrier
__device__ float    g_part[GRID];

// ---------------- helpers ----------------
__device__ __forceinline__ float ex2f(float x) {
    float y; asm("ex2.approx.ftz.f32 %0, %1;" : "=f"(y) : "f"(x)); return y;
}
__device__ __forceinline__ float lg2f(float x) {
    float y; asm("lg2.approx.f32 %0, %1;" : "=f"(y) : "f"(x)); return y;
}
__device__ __forceinline__ void lse_merge(float& m, float& s, float m2, float s2) {
    float M = fmaxf(m, m2);
    s = fmaf(s, ex2f(m - M), s2 * ex2f(m2 - M));
    m = M;
}
// per-batch barrier: monotonic counter, release on arrive, acquire on spin
__device__ __forceinline__ void batch_barrier(int b, unsigned target) {
    __syncthreads();
    if (threadIdx.x == 0) {
        unsigned old;
        asm volatile("atom.release.gpu.global.add.u32 %0, [%1], 1;"
                     : "=r"(old) : "l"(&g_bar[b]) : "memory");
        unsigned cur;
        do {
            asm volatile("ld.acquire.gpu.global.u32 %0, [%1];"
                         : "=r"(cur) : "l"(&g_bar[b]) : "memory");
            if (cur >= target) break;
            __nanosleep(32);
        } while (true);
    }
    __syncthreads();
}

// ---------------- init: norms + state reset ----------------
__global__ __launch_bounds__(256) void init_kernel(const float* __restrict__ x,
                                                   const float* __restrict__ y) {
    int tid = threadIdx.x, w = tid >> 5, lane = tid & 31;
    int r = blockIdx.x * 8 + w;                 // 0..32767
    bool is_x = (r < BATCH * NPTS);
    const float* src = is_x ? (x + (size_t)r * DIM)
                            : (y + (size_t)(r - BATCH * NPTS) * DIM);
    float a = src[lane], b = src[lane + 32];
    float sq = a * a + b * b;
    #pragma unroll
    for (int o = 16; o; o >>= 1) sq += __shfl_xor_sync(0xffffffffu, sq, o);
    if (lane == 0) {
        if (is_x) g_xn[r] = sq; else g_yn[r - BATCH * NPTS] = sq;
    }
    int g = blockIdx.x * 256 + tid;
    if (g < BATCH * NPTS) g_vL[g] = 0.0f;
    if (g < BATCH) g_bar[g] = 0u;
}

// ---------------- build C = |x|^2 + |y|^2 - 2 x.y ----------------
__global__ __launch_bounds__(256) void c_kernel(const float* __restrict__ x,
                                                const float* __restrict__ y) {
    __shared__ float xs[64][65];
    __shared__ float ys[64][65];
    int tid = threadIdx.x;
    int b = blockIdx.z, i0 = blockIdx.y * 64, j0 = blockIdx.x * 64;
    const float* xb = x + ((size_t)(b * NPTS + i0)) * DIM;
    const float* yb = y + ((size_t)(b * NPTS + j0)) * DIM;
    #pragma unroll
    for (int t = 0; t < 4; t++) {
        int e = tid + t * 256;
        int row = e >> 4, c4 = (e & 15) * 4;
        float4 vx = *(const float4*)(xb + row * DIM + c4);
        xs[row][c4] = vx.x; xs[row][c4 + 1] = vx.y; xs[row][c4 + 2] = vx.z; xs[row][c4 + 3] = vx.w;
        float4 vy = *(const float4*)(yb + row * DIM + c4);
        ys[row][c4] = vy.x; ys[row][c4 + 1] = vy.y; ys[row][c4 + 2] = vy.z; ys[row][c4 + 3] = vy.w;
    }
    __syncthreads();
    int tx = tid & 15, ty = tid >> 4;
    float acc[4][4];
    #pragma unroll
    for (int r = 0; r < 4; r++)
        #pragma unroll
        for (int c = 0; c < 4; c++) acc[r][c] = 0.0f;
    #pragma unroll 16
    for (int d = 0; d < 64; d++) {
        float a0 = xs[ty * 4 + 0][d], a1 = xs[ty * 4 + 1][d];
        float a2 = xs[ty * 4 + 2][d], a3 = xs[ty * 4 + 3][d];
        float b0 = ys[tx * 4 + 0][d], b1 = ys[tx * 4 + 1][d];
        float b2 = ys[tx * 4 + 2][d], b3 = ys[tx * 4 + 3][d];
        acc[0][0] = fmaf(a0, b0, acc[0][0]); acc[0][1] = fmaf(a0, b1, acc[0][1]);
        acc[0][2] = fmaf(a0, b2, acc[0][2]); acc[0][3] = fmaf(a0, b3, acc[0][3]);
        acc[1][0] = fmaf(a1, b0, acc[1][0]); acc[1][1] = fmaf(a1, b1, acc[1][1]);
        acc[1][2] = fmaf(a1, b2, acc[1][2]); acc[1][3] = fmaf(a1, b3, acc[1][3]);
        acc[2][0] = fmaf(a2, b0, acc[2][0]); acc[2][1] = fmaf(a2, b1, acc[2][1]);
        acc[2][2] = fmaf(a2, b2, acc[2][2]); acc[2][3] = fmaf(a2, b3, acc[2][3]);
        acc[3][0] = fmaf(a3, b0, acc[3][0]); acc[3][1] = fmaf(a3, b1, acc[3][1]);
        acc[3][2] = fmaf(a3, b2, acc[3][2]); acc[3][3] = fmaf(a3, b3, acc[3][3]);
    }
    float* Cb = g_C + ((size_t)b << 20);
    float yn0 = g_yn[b * NPTS + j0 + tx * 4 + 0];
    float yn1 = g_yn[b * NPTS + j0 + tx * 4 + 1];
    float yn2 = g_yn[b * NPTS + j0 + tx * 4 + 2];
    float yn3 = g_yn[b * NPTS + j0 + tx * 4 + 3];
    #pragma unroll
    for (int r = 0; r < 4; r++) {
        int i = i0 + ty * 4 + r;
        float xni = g_xn[b * NPTS + i];
        float4 o;
        o.x = xni + yn0 - 2.0f * acc[r][0];
        o.y = xni + yn1 - 2.0f * acc[r][1];
        o.z = xni + yn2 - 2.0f * acc[r][2];
        o.w = xni + yn3 - 2.0f * acc[r][3];
        *(float4*)(Cb + (size_t)i * NPTS + j0 + tx * 4) = o;
    }
}

// ---------------- persistent Sinkhorn kernel ----------------
// 512 CTAs (32 per batch), all co-resident (4/SM guaranteed). Each CTA owns
// 32 rows (row phase, warp/row) and 32 cols (col phase, thread = col x 128
// rows). Per-batch barriers between phases; cost folded in at the end.
__global__ __launch_bounds__(256, 4) void sink_kernel(float* __restrict__ out) {
    __shared__ float sh[NPTS];       // vL (row/cost phases) or uL (col phase)
    __shared__ float sh_m[256];
    __shared__ float sh_s[256];
    int tid  = threadIdx.x, w = tid >> 5, lane = tid & 31;
    int b    = blockIdx.x >> 5;
    int idx  = blockIdx.x & 31;
    const float* Cb = g_C + ((size_t)b << 20);
    float* uLb = g_uL + (b << 10);
    float* vLb = g_vL + (b << 10);
    unsigned nbar = 0;

    for (int it = 0; it < ITERS; ++it) {
        // ======== row phase: uL_i = LOG2_A - log2 sum_j 2^(vL_j - C_ij*L2E) ========
        #pragma unroll
        for (int t = 0; t < 4; t++) sh[tid + t * 256] = vLb[tid + t * 256];
        __syncthreads();
        #pragma unroll 1
        for (int k = 0; k < 4; k++) {
            int r = idx * 32 + k * 8 + w;
            const float* Crow = Cb + ((size_t)r << 10);
            float wv[32];
            #pragma unroll
            for (int q = 0; q < 8; q++) {
                int j = q * 128 + lane * 4;
                float4 c  = *(const float4*)(Crow + j);
                float4 vl = *(const float4*)(sh + j);
                wv[q * 4 + 0] = fmaf(c.x, -L2E_EPS, vl.x);
                wv[q * 4 + 1] = fmaf(c.y, -L2E_EPS, vl.y);
                wv[q * 4 + 2] = fmaf(c.z, -L2E_EPS, vl.z);
                wv[q * 4 + 3] = fmaf(c.w, -L2E_EPS, vl.w);
            }
            float gm[4];
            #pragma unroll
            for (int q = 0; q < 4; q++) {
                float t0 = fmaxf(wv[q * 8 + 0], wv[q * 8 + 1]);
                float t1 = fmaxf(wv[q * 8 + 2], wv[q * 8 + 3]);
                float t2 = fmaxf(wv[q * 8 + 4], wv[q * 8 + 5]);
                float t3 = fmaxf(wv[q * 8 + 6], wv[q * 8 + 7]);
                gm[q] = fmaxf(fmaxf(t0, t1), fmaxf(t2, t3));
            }
            float M = fmaxf(fmaxf(gm[0], gm[1]), fmaxf(gm[2], gm[3]));
            #pragma unroll
            for (int o = 16; o; o >>= 1) M = fmaxf(M, __shfl_xor_sync(0xffffffffu, M, o));
            float thr = M - SKIP_THR;
            float s = 0.0f;
            #pragma unroll
            for (int q = 0; q < 4; q++) {
                if (__any_sync(0xffffffffu, gm[q] > thr)) {
                    float s0 = ex2f(wv[q * 8 + 0] - M) + ex2f(wv[q * 8 + 4] - M);
                    float s1 = ex2f(wv[q * 8 + 1] - M) + ex2f(wv[q * 8 + 5] - M);
                    float s2 = ex2f(wv[q * 8 + 2] - M) + ex2f(wv[q * 8 + 6] - M);
                    float s3 = ex2f(wv[q * 8 + 3] - M) + ex2f(wv[q * 8 + 7] - M);
                    s += (s0 + s1) + (s2 + s3);
                }
            }
            #pragma unroll
            for (int o = 16; o; o >>= 1) s += __shfl_xor_sync(0xffffffffu, s, o);
            if (lane == 0) uLb[r] = LOG2_A - (M + lg2f(s));
        }
        batch_barrier(b, 32u * (++nbar));

        // ======== col phase: vL_j = LOG2_A - log2 sum_i 2^(uL_i - C_ij*L2E) ========
        #pragma unroll
        for (int t = 0; t < 4; t++) sh[tid + t * 256] = uLb[tid + t * 256];
        __syncthreads();
        {
            int c = tid & 31;
            int g = tid >> 5;                     // 8 row groups of 128
            const float* Cp = Cb + (((size_t)g * 128) << 10) + (idx * 32 + c);
            float m = -1e30f, s = 0.0f;
            #pragma unroll 1
            for (int ch = 0; ch < 4; ch++) {
                const float* p = Cp + (((size_t)ch * 32) << 10);
                float wv[32];
                #pragma unroll
                for (int r = 0; r < 32; r++) wv[r] = __ldg(p + ((size_t)r << 10));
                #pragma unroll
                for (int r = 0; r < 32; r++)
                    wv[r] = fmaf(wv[r], -L2E_EPS, sh[g * 128 + ch * 32 + r]);
                float t0 = fmaxf(wv[0], wv[1]),   t1 = fmaxf(wv[2], wv[3]);
                float t2 = fmaxf(wv[4], wv[5]),   t3 = fmaxf(wv[6], wv[7]);
                float t4 = fmaxf(wv[8], wv[9]),   t5 = fmaxf(wv[10], wv[11]);
                float t6 = fmaxf(wv[12], wv[13]), t7 = fmaxf(wv[14], wv[15]);
                float u0 = fmaxf(wv[16], wv[17]), u1 = fmaxf(wv[18], wv[19]);
                float u2 = fmaxf(wv[20], wv[21]), u3 = fmaxf(wv[22], wv[23]);
                float u4 = fmaxf(wv[24], wv[25]), u5 = fmaxf(wv[26], wv[27]);
                float u6 = fmaxf(wv[28], wv[29]), u7 = fmaxf(wv[30], wv[31]);
                t0 = fmaxf(t0, t1); t2 = fmaxf(t2, t3); t4 = fmaxf(t4, t5); t6 = fmaxf(t6, t7);
                u0 = fmaxf(u0, u1); u2 = fmaxf(u2, u3); u4 = fmaxf(u4, u5); u6 = fmaxf(u6, u7);
                float mk = fmaxf(fmaxf(fmaxf(t0, t2), fmaxf(t4, t6)),
                                 fmaxf(fmaxf(u0, u2), fmaxf(u4, u6)));
                float s0 = ex2f(wv[0] - mk)  + ex2f(wv[4] - mk);
                float s1 = ex2f(wv[1] - mk)  + ex2f(wv[5] - mk);
                float s2 = ex2f(wv[2] - mk)  + ex2f(wv[6] - mk);
                float s3 = ex2f(wv[3] - mk)  + ex2f(wv[7] - mk);
                #pragma unroll
                for (int r = 8; r < 32; r += 8) {
                    s0 += ex2f(wv[r + 0] - mk) + ex2f(wv[r + 4] - mk);
                    s1 += ex2f(wv[r + 1] - mk) + ex2f(wv[r + 5] - mk);
                    s2 += ex2f(wv[r + 2] - mk) + ex2f(wv[r + 6] - mk);
                    s3 += ex2f(wv[r + 3] - mk) + ex2f(wv[r + 7] - mk);
                }
                lse_merge(m, s, mk, (s0 + s1) + (s2 + s3));
            }
            sh_m[tid] = m; sh_s[tid] = s;
        }
        __syncthreads();
        if (tid < 32) {
            float M = sh_m[tid], S = sh_s[tid];
            #pragma unroll
            for (int gg = 1; gg < 8; gg++) lse_merge(M, S, sh_m[gg * 32 + tid], sh_s[gg * 32 + tid]);
            vLb[idx * 32 + tid] = LOG2_A - (M + lg2f(S));
        }
        batch_barrier(b, 32u * (++nbar));
    }

    // ======== cost: out[b] = sum_ij 2^(uL+vL-C*L2E) * C ========
    #pragma unroll
    for (int t = 0; t < 4; t++) sh[tid + t * 256] = vLb[tid + t * 256];
    __syncthreads();
    float acc = 0.0f;
    #pragma unroll 1
    for (int k = 0; k < 4; k++) {
        int r = idx * 32 + k * 8 + w;
        float uL = uLb[r];
        const float* Crow = Cb + ((size_t)r << 10);
        #pragma unroll
        for (int q = 0; q < 8; q++) {
            int j = q * 128 + lane * 4;
            float4 c  = *(const float4*)(Crow + j);
            float4 vl = *(const float4*)(sh + j);
            float p;
            p = ex2f(fmaf(c.x, -L2E_EPS, uL + vl.x)); acc = fmaf(p, c.x, acc);
            p = ex2f(fmaf(c.y, -L2E_EPS, uL + vl.y)); acc = fmaf(p, c.y, acc);
            p = ex2f(fmaf(c.z, -L2E_EPS, uL + vl.z)); acc = fmaf(p, c.z, acc);
            p = ex2f(fmaf(c.w, -L2E_EPS, uL + vl.w)); acc = fmaf(p, c.w, acc);
        }
    }
    #pragma unroll
    for (int o = 16; o; o >>= 1) acc += __shfl_xor_sync(0xffffffffu, acc, o);
    if (lane == 0) sh_m[w] = acc;
    __syncthreads();
    if (tid == 0) {
        float t = 0.0f;
        #pragma unroll
        for (int i = 0; i < 8; i++) t += sh_m[i];
        g_part[blockIdx.x] = t;
    }
    batch_barrier(b, 32u * (++nbar));
    if (idx == 0 && tid == 0) {
        float t = 0.0f;
        #pragma unroll
        for (int k = 0; k < 32; k++) t += g_part[b * 32 + k];
        out[b] = t;
    }
}

// ---------------- launch ----------------
extern "C" void kernel_launch(void* const* d_in, const int* in_sizes, int n_in,
                              void* d_out, int out_size) {
    (void)in_sizes; (void)n_in; (void)out_size;
    const float* x = (const float*)d_in[0];
    const float* y = (const float*)d_in[1];
    float* out = (float*)d_out;

    init_kernel<<<4096, 256>>>(x, y);
    c_kernel<<<dim3(16, 16, 16), 256>>>(x, y);
    sink_kernel<<<GRID, 256>>>(out);
}